// round 9
// baseline (speedup 1.0000x reference)
#include <cuda_runtime.h>
#include <cuda_fp16.h>
#include <math.h>

#define NN 50000
#define EE 800000
#define GG 1024
#define DD 64
#define DIN 9
#define NBLK ((NN + 255) / 256)   // 196

// ---------------- scratch (static device globals; no allocation) ------------
__device__ int      g_deg[NN];        // in-edge count (no self-loop)
__device__ float    g_dinv[NN];       // rsqrt(in+1)
__device__ int      g_ptr[NN];        // CSR (by destination) segment start
__device__ int      g_pos[NN];        // fill cursor (seeded with start)
__device__ int      g_srcs[EE];       // CSR column: source node per in-edge
__device__ int      g_total;          // bump allocator
__device__ __align__(16) __half g_feat[NN * DD];  // features, pre-scaled by dinv
__device__ float    g_agg[NN * DD];   // aggregation output (fp32)
__device__ unsigned g_gmax[GG * DD];
__device__ float    g_gsum[GG * DD];
__device__ int      g_gcnt[GG];

// ---------------- setup -----------------------------------------------------
__global__ void k_init() {
    int i = blockIdx.x * blockDim.x + threadIdx.x;   // grid covers 65536
    if (i < NN) g_deg[i] = 0;
    if (i < GG * DD) { g_gmax[i] = 0u; g_gsum[i] = 0.f; }
    if (i < GG) g_gcnt[i] = 0;
    if (i == 0) g_total = 0;
}

// 4 edges per thread (int4 loads, 4 independent atomics in flight)
__global__ void k_count(const int* __restrict__ ei, const int* __restrict__ batch) {
    int t = blockIdx.x * blockDim.x + threadIdx.x;
    int e4 = t * 4;
    if (e4 < EE) {
        int4 d = *(const int4*)(ei + EE + e4);       // destinations
        atomicAdd(&g_deg[d.x], 1);
        atomicAdd(&g_deg[d.y], 1);
        atomicAdd(&g_deg[d.z], 1);
        atomicAdd(&g_deg[d.w], 1);
    }
    if (t < NN) atomicAdd(&g_gcnt[batch[t]], 1);     // nodes-per-graph
}

// warp-scan segment allocation: 1 global atomic per warp instead of per thread
__global__ void k_alloc() {
    int i = blockIdx.x * blockDim.x + threadIdx.x;
    int lane = threadIdx.x & 31;
    int c = (i < NN) ? g_deg[i] : 0;
    int sc = c;                                      // inclusive warp scan
#pragma unroll
    for (int o = 1; o < 32; o <<= 1) {
        int t = __shfl_up_sync(0xffffffffu, sc, o);
        if (lane >= o) sc += t;
    }
    int base = 0;
    if (lane == 31) base = atomicAdd(&g_total, sc);
    base = __shfl_sync(0xffffffffu, base, 31);
    if (i < NN) {
        int s = base + sc - c;
        g_ptr[i] = s;
        g_pos[i] = s;                                // fill cursor
        g_dinv[i] = rsqrtf((float)(c + 1));
    }
}

// 4 edges per thread (int4 loads of both src and dst rows)
__global__ void k_fill(const int* __restrict__ ei) {
    int e4 = (blockIdx.x * blockDim.x + threadIdx.x) * 4;
    if (e4 < EE) {
        int4 s = *(const int4*)(ei + e4);            // sources
        int4 d = *(const int4*)(ei + EE + e4);       // destinations
        int p0 = atomicAdd(&g_pos[d.x], 1);
        int p1 = atomicAdd(&g_pos[d.y], 1);
        int p2 = atomicAdd(&g_pos[d.z], 1);
        int p3 = atomicAdd(&g_pos[d.w], 1);
        g_srcs[p0] = s.x;
        g_srcs[p1] = s.y;
        g_srcs[p2] = s.z;
        g_srcs[p3] = s.w;
    }
}

// ---------------- layer-0 aggregation over raw 9-dim x ----------------------
// out[v] = dinv[v] * ( sum_s dinv[s]*x[s] + dinv[v]*x[v] )
__global__ void k_agg9(const float* __restrict__ x, float* __restrict__ out) {
    int w = (blockIdx.x * blockDim.x + threadIdx.x) >> 5;
    int lane = threadIdx.x & 31;
    if (w >= NN) return;
    int start = g_ptr[w], cnt = g_deg[w];
    float a = 0.f;
    for (int base = 0; base < cnt; base += 32) {
        int m = min(32, cnt - base);
        int sl = 0; float dl = 0.f;
        if (lane < m) { sl = g_srcs[start + base + lane]; dl = g_dinv[sl]; }
        for (int i = 0; i < m; i++) {
            int s   = __shfl_sync(0xffffffffu, sl, i);
            float ws = __shfl_sync(0xffffffffu, dl, i);
            if (lane < DIN) a += ws * x[s * DIN + lane];
        }
    }
    float di = g_dinv[w];
    if (lane < DIN) {
        a += di * x[w * DIN + lane];
        out[w * DIN + lane] = di * a;
    }
}

// ---------------- aggregation on pre-scaled fp16 features --------------------
// g_feat holds fs[v] = dinv[v]*h[v];  out[v] = dinv[v]*( sum_s fs[s] + fs[v] )
// Quad-edge layout: 8 lanes per edge, one uint4 (8 halves) per lane per edge.
__global__ void k_agg64h(float* __restrict__ out) {
    int w = (blockIdx.x * blockDim.x + threadIdx.x) >> 5;
    int lane = threadIdx.x & 31;
    if (w >= NN) return;
    int grp = lane >> 3;          // which edge within quad (0..3)
    int sub = lane & 7;           // dim-chunk (8 halves each)
    int start = g_ptr[w], cnt = g_deg[w];
    const uint4* __restrict__ F = (const uint4*)g_feat;   // node row = 8 uint4
    float acc[8];
#pragma unroll
    for (int j = 0; j < 8; j++) acc[j] = 0.f;

    for (int base = 0; base < cnt; base += 32) {
        int m = min(32, cnt - base);
        int sl = (lane < m) ? g_srcs[start + base + lane] : 0;
        for (int i = 0; i < m; i += 4) {
            int e = i + grp;
            int s = __shfl_sync(0xffffffffu, sl, e & 31);
            if (e < m) {
                uint4 v = F[s * 8 + sub];
                float2 f0 = __half22float2(*(const __half2*)&v.x);
                float2 f1 = __half22float2(*(const __half2*)&v.y);
                float2 f2 = __half22float2(*(const __half2*)&v.z);
                float2 f3 = __half22float2(*(const __half2*)&v.w);
                acc[0] += f0.x; acc[1] += f0.y;
                acc[2] += f1.x; acc[3] += f1.y;
                acc[4] += f2.x; acc[5] += f2.y;
                acc[6] += f3.x; acc[7] += f3.y;
            }
        }
    }
    // reduce across the 4 edge-groups (lanes sub, sub+8, sub+16, sub+24)
#pragma unroll
    for (int j = 0; j < 8; j++) {
        acc[j] += __shfl_xor_sync(0xffffffffu, acc[j], 8);
        acc[j] += __shfl_xor_sync(0xffffffffu, acc[j], 16);
    }
    if (grp == 0) {                                       // lanes 0..7 write
        uint4 v = F[w * 8 + sub];                         // self term fs[v]
        float2 f0 = __half22float2(*(const __half2*)&v.x);
        float2 f1 = __half22float2(*(const __half2*)&v.y);
        float2 f2 = __half22float2(*(const __half2*)&v.z);
        float2 f3 = __half22float2(*(const __half2*)&v.w);
        acc[0] += f0.x; acc[1] += f0.y;
        acc[2] += f1.x; acc[3] += f1.y;
        acc[4] += f2.x; acc[5] += f2.y;
        acc[6] += f3.x; acc[7] += f3.y;
        float di = g_dinv[w];
        float4 o0 = {di * acc[0], di * acc[1], di * acc[2], di * acc[3]};
        float4 o1 = {di * acc[4], di * acc[5], di * acc[6], di * acc[7]};
        float4* op = (float4*)(out + w * DD + sub * 8);
        op[0] = o0;
        op[1] = o1;
    }
}

// ---------------- layer-0 GEMM (K=9): thread-per-node ------------------------
__global__ __launch_bounds__(256) void k_gemm9(const float* __restrict__ A,
        const float* __restrict__ W, const float* __restrict__ b) {
    __shared__ float Ws[DIN * DD];
    __shared__ float bs[DD];
    int tid = threadIdx.x;
    for (int i = tid; i < DIN * DD; i += 256) Ws[i] = W[i];
    if (tid < DD) bs[tid] = b[tid];
    __syncthreads();
    int node = blockIdx.x * 256 + tid;
    if (node >= NN) return;
    float a[DIN];
#pragma unroll
    for (int k = 0; k < DIN; k++) a[k] = A[node * DIN + k];
    float di = g_dinv[node];
    __half2* o = (__half2*)(g_feat + node * DD);
#pragma unroll
    for (int c = 0; c < DD; c += 2) {
        float a0 = bs[c], a1 = bs[c + 1];
#pragma unroll
        for (int k = 0; k < DIN; k++) {
            a0 = fmaf(a[k], Ws[k * DD + c],     a0);
            a1 = fmaf(a[k], Ws[k * DD + c + 1], a1);
        }
        o[c >> 1] = __floats2half2_rn(di * tanhf(a0), di * tanhf(a1));
    }
}

// ---------------- K=64 GEMM: 64-node tile, 4x4 register blocking -------------
// POOL=0: write tanh(.)*dinv as fp16 features. POOL=1: fused graph pooling.
template <int POOL>
__global__ __launch_bounds__(256) void k_gemm64(const float* __restrict__ A,
        const float* __restrict__ W, const float* __restrict__ b,
        const int* __restrict__ batch) {
    __shared__ float As[DD][DD + 4];   // transposed A tile, padded
    __shared__ float Ws[DD * DD];
    int tid = threadIdx.x;
    int node0 = blockIdx.x * DD;
    for (int i = tid; i < DD * DD; i += 256) {
        int n = i >> 6, k = i & 63;
        int node = node0 + n;
        As[k][n] = (node < NN) ? A[node * DD + k] : 0.f;
        Ws[i] = W[i];
    }
    __syncthreads();
    int n0 = (tid >> 4) << 2;
    int c0 = (tid & 15) << 2;
    float4 bv = *(const float4*)(b + c0);
    float acc[4][4];
#pragma unroll
    for (int i = 0; i < 4; i++) {
        acc[i][0] = bv.x; acc[i][1] = bv.y; acc[i][2] = bv.z; acc[i][3] = bv.w;
    }
#pragma unroll
    for (int k = 0; k < DD; k++) {
        float4 av = *(const float4*)&As[k][n0];
        float4 wv = *(const float4*)&Ws[k * DD + c0];
        float aa[4] = {av.x, av.y, av.z, av.w};
        float ww[4] = {wv.x, wv.y, wv.z, wv.w};
#pragma unroll
        for (int i = 0; i < 4; i++)
#pragma unroll
            for (int j = 0; j < 4; j++)
                acc[i][j] = fmaf(aa[i], ww[j], acc[i][j]);
    }
#pragma unroll
    for (int i = 0; i < 4; i++) {
        int node = node0 + n0 + i;
        if (node >= NN) continue;
        float v[4];
#pragma unroll
        for (int j = 0; j < 4; j++) v[j] = tanhf(acc[i][j]);
        if (POOL) {
            int g = batch[node] * DD + c0;
#pragma unroll
            for (int j = 0; j < 4; j++) {
                float x = v[j];
                unsigned enc = (x >= 0.f) ? (__float_as_uint(x) | 0x80000000u)
                                          : ~__float_as_uint(x);
                atomicMax(&g_gmax[g + j], enc);
                atomicAdd(&g_gsum[g + j], x);
            }
        } else {
            float di = g_dinv[node];
            __half2* o = (__half2*)(g_feat + node * DD + c0);
            o[0] = __floats2half2_rn(di * v[0], di * v[1]);
            o[1] = __floats2half2_rn(di * v[2], di * v[3]);
        }
    }
}

// ---------------- readout ----------------------------------------------------
__global__ void k_out(const float* __restrict__ Wout, const float* __restrict__ bout,
                      float* __restrict__ out) {
    int g = blockIdx.x;
    int lane = threadIdx.x;
    float cnt = fmaxf((float)g_gcnt[g], 1.f);
    float s = 0.f;
    for (int f = lane; f < DD; f += 32) {
        unsigned e = g_gmax[g * DD + f];
        float mx = (e & 0x80000000u) ? __uint_as_float(e & 0x7FFFFFFFu)
                                     : __uint_as_float(~e);
        float mn = g_gsum[g * DD + f] / cnt;
        s += mx * Wout[f] + mn * Wout[DD + f];
    }
#pragma unroll
    for (int o = 16; o > 0; o >>= 1) s += __shfl_down_sync(0xFFFFFFFFu, s, o);
    if (lane == 0) out[g] = s + bout[0];
}

// ---------------- launch ----------------------------------------------------
extern "C" void kernel_launch(void* const* d_in, const int* in_sizes, int n_in,
                              void* d_out, int out_size) {
    const float* x     = (const float*)d_in[0];
    const int*   ei    = (const int*)d_in[1];
    const int*   batch = (const int*)d_in[2];
    const float* W0    = (const float*)d_in[3];
    const float* b0    = (const float*)d_in[4];
    const float* W1    = (const float*)d_in[5];
    const float* b1    = (const float*)d_in[6];
    const float* W2    = (const float*)d_in[7];
    const float* b2    = (const float*)d_in[8];
    const float* W3    = (const float*)d_in[9];
    const float* b3    = (const float*)d_in[10];
    const float* Wout  = (const float*)d_in[11];
    const float* bout  = (const float*)d_in[12];
    float* out = (float*)d_out;

    float* aggp;
    cudaGetSymbolAddress((void**)&aggp, g_agg);

    const int EB4  = (EE / 4 + 255) / 256;    // 782  (4 edges/thread)
    const int CB   = (NN + 255) / 256 > EB4 ? (NN + 255) / 256 : EB4;  // covers both
    const int AGGB = (NN * 32 + 255) / 256;   // 6250 (warp per node)
    const int GB   = (NN + DD - 1) / DD;      // 782  (64-node GEMM tiles)

    k_init<<<256, 256>>>();
    k_count<<<CB, 256>>>(ei, batch);
    k_alloc<<<NBLK, 256>>>();
    k_fill<<<EB4, 256>>>(ei);

    // layer 0: aggregate raw 9-dim features, GEMM K=9, store dinv-scaled fp16
    k_agg9<<<AGGB, 256>>>(x, aggp);
    k_gemm9<<<NBLK, 256>>>(aggp, W0, b0);
    // layers 1..2
    k_agg64h<<<AGGB, 256>>>(aggp);
    k_gemm64<0><<<GB, 256>>>(aggp, W1, b1, nullptr);
    k_agg64h<<<AGGB, 256>>>(aggp);
    k_gemm64<0><<<GB, 256>>>(aggp, W2, b2, nullptr);
    // layer 3 with fused pooling
    k_agg64h<<<AGGB, 256>>>(aggp);
    k_gemm64<1><<<GB, 256>>>(aggp, W3, b3, batch);

    k_out<<<GG, 32>>>(Wout, bout, out);
}